// round 12
// baseline (speedup 1.0000x reference)
#include <cuda_runtime.h>
#include <math.h>

// Cosine similarity per row: out[n] = dot(p[n],h[n]) / (max(||p||,eps)*max(||h||,eps))
// N = 65536 rows, D = 1024 floats (= 256 float4).
// One WARP per row. Software-pipelined in two half-batches of 8 loads
// (4 p-float4 + 4 h-float4 each): batch1 loads are issued before batch0 is
// consumed, so ~16 loads are in flight at the seam while peak live registers
// stay ~32 data regs. launch_bounds(256,5) -> 51-reg budget -> 40 warps/SM
// (vs 32 at R4's 64-reg version), smoothing SM-wide outstanding-load duty cycle.

#define D_DIM 1024
#define F4_PER_ROW (D_DIM / 4)        // 256
#define THREADS 256                   // 8 warps -> 8 rows per CTA
#define ROWS_PER_CTA 8
#define EPS 1e-12f

__global__ __launch_bounds__(THREADS, 5)
void cosine_sim_warp_kernel(const float4* __restrict__ p,
                            const float4* __restrict__ h,
                            float* __restrict__ out)
{
    const int warp = threadIdx.x >> 5;
    const int lane = threadIdx.x & 31;
    const long long row = (long long)blockIdx.x * ROWS_PER_CTA + warp;

    const float4* __restrict__ prow = p + row * F4_PER_ROW + lane;
    const float4* __restrict__ hrow = h + row * F4_PER_ROW + lane;

    // ---- batch 0 loads (8 independent LDG.128) ----
    float4 pv0[4], hv0[4];
    #pragma unroll
    for (int i = 0; i < 4; i++) pv0[i] = __ldcs(prow + i * 32);
    #pragma unroll
    for (int i = 0; i < 4; i++) hv0[i] = __ldcs(hrow + i * 32);

    // ---- batch 1 loads issued BEFORE consuming batch 0 ----
    float4 pv1[4], hv1[4];
    #pragma unroll
    for (int i = 0; i < 4; i++) pv1[i] = __ldcs(prow + (i + 4) * 32);
    #pragma unroll
    for (int i = 0; i < 4; i++) hv1[i] = __ldcs(hrow + (i + 4) * 32);

    float dot = 0.0f, pp = 0.0f, hh = 0.0f;

    // consume batch 0 (frees its 32 regs for the scheduler)
    #pragma unroll
    for (int i = 0; i < 4; i++) {
        dot = fmaf(pv0[i].x, hv0[i].x, dot);
        dot = fmaf(pv0[i].y, hv0[i].y, dot);
        dot = fmaf(pv0[i].z, hv0[i].z, dot);
        dot = fmaf(pv0[i].w, hv0[i].w, dot);
        pp  = fmaf(pv0[i].x, pv0[i].x, pp);
        pp  = fmaf(pv0[i].y, pv0[i].y, pp);
        pp  = fmaf(pv0[i].z, pv0[i].z, pp);
        pp  = fmaf(pv0[i].w, pv0[i].w, pp);
        hh  = fmaf(hv0[i].x, hv0[i].x, hh);
        hh  = fmaf(hv0[i].y, hv0[i].y, hh);
        hh  = fmaf(hv0[i].z, hv0[i].z, hh);
        hh  = fmaf(hv0[i].w, hv0[i].w, hh);
    }

    // consume batch 1
    #pragma unroll
    for (int i = 0; i < 4; i++) {
        dot = fmaf(pv1[i].x, hv1[i].x, dot);
        dot = fmaf(pv1[i].y, hv1[i].y, dot);
        dot = fmaf(pv1[i].z, hv1[i].z, dot);
        dot = fmaf(pv1[i].w, hv1[i].w, dot);
        pp  = fmaf(pv1[i].x, pv1[i].x, pp);
        pp  = fmaf(pv1[i].y, pv1[i].y, pp);
        pp  = fmaf(pv1[i].z, pv1[i].z, pp);
        pp  = fmaf(pv1[i].w, pv1[i].w, pp);
        hh  = fmaf(hv1[i].x, hv1[i].x, hh);
        hh  = fmaf(hv1[i].y, hv1[i].y, hh);
        hh  = fmaf(hv1[i].z, hv1[i].z, hh);
        hh  = fmaf(hv1[i].w, hv1[i].w, hh);
    }

    // Warp-level tree reduction of the three partials.
    #pragma unroll
    for (int offset = 16; offset > 0; offset >>= 1) {
        dot += __shfl_xor_sync(0xFFFFFFFFu, dot, offset);
        pp  += __shfl_xor_sync(0xFFFFFFFFu, pp,  offset);
        hh  += __shfl_xor_sync(0xFFFFFFFFu, hh,  offset);
    }

    if (lane == 0) {
        float pn = fmaxf(sqrtf(pp), EPS);
        float hn = fmaxf(sqrtf(hh), EPS);
        out[row] = dot / (pn * hn);
    }
}

extern "C" void kernel_launch(void* const* d_in, const int* in_sizes, int n_in,
                              void* d_out, int out_size) {
    const float4* p = (const float4*)d_in[0];
    const float4* h = (const float4*)d_in[1];
    float* out = (float*)d_out;

    const int n_rows = in_sizes[0] / D_DIM;          // 65536
    const int n_blocks = n_rows / ROWS_PER_CTA;      // 8192
    cosine_sim_warp_kernel<<<n_blocks, THREADS>>>(p, h, out);
}